// round 1
// baseline (speedup 1.0000x reference)
#include <cuda_runtime.h>
#include <math.h>

// Problem constants
#define B_ 4
#define L_ 2048
#define D_ 256
#define H_ 4096
#define M_ (B_ * L_)          // 8192 rows for both GEMMs
#define CHUNK_ 128
#define NC_ (L_ / CHUNK_)     // 16 chunks

// Scratch: b / h intermediate [M_, H_] = 128 MB, plus carry buffers.
__device__ float g_b[(size_t)M_ * H_];
__device__ float g_carry[B_ * NC_ * H_];
__device__ float g_hprev[B_ * NC_ * H_];

// ---------------------------------------------------------------------------
// SGEMM (NT): C[M,N] = A[M,K] * Bw[N,K]^T + bias[N]
// Both operands row-major with K contiguous. M%BM==0, N%BN==0, K%BK==0.
// ---------------------------------------------------------------------------
template <int BM, int BN, int BK, int TM, int TN>
__global__ __launch_bounds__(256, 2)
void sgemm_nt_bias(const float* __restrict__ A, const float* __restrict__ Bw,
                   const float* __restrict__ bias, float* __restrict__ C,
                   int M, int N, int K)
{
    __shared__ float As[BK][BM + 4];
    __shared__ float Bs[BK][BN + 4];

    const int tid = threadIdx.x;               // 256 threads
    const int bm = blockIdx.y * BM;
    const int bn = blockIdx.x * BN;
    const int tx = tid % (BN / TN);            // 16
    const int ty = tid / (BN / TN);            // 16

    float acc[TM][TN];
#pragma unroll
    for (int i = 0; i < TM; i++)
#pragma unroll
        for (int j = 0; j < TN; j++) acc[i][j] = 0.0f;

    const int lrow = tid >> 2;                 // 0..63
    const int lk = (tid & 3) * 4;              // 0,4,8,12  (covers BK=16)

    for (int k0 = 0; k0 < K; k0 += BK) {
        // Load A tile [BM x BK] (transposed into smem)
#pragma unroll
        for (int i = 0; i < BM / 64; i++) {
            int row = lrow + i * 64;
            float4 v = *reinterpret_cast<const float4*>(
                &A[(size_t)(bm + row) * K + k0 + lk]);
            As[lk + 0][row] = v.x; As[lk + 1][row] = v.y;
            As[lk + 2][row] = v.z; As[lk + 3][row] = v.w;
        }
        // Load Bw tile [BN x BK]
#pragma unroll
        for (int i = 0; i < BN / 64; i++) {
            int row = lrow + i * 64;
            float4 v = *reinterpret_cast<const float4*>(
                &Bw[(size_t)(bn + row) * K + k0 + lk]);
            Bs[lk + 0][row] = v.x; Bs[lk + 1][row] = v.y;
            Bs[lk + 2][row] = v.z; Bs[lk + 3][row] = v.w;
        }
        __syncthreads();

#pragma unroll
        for (int k = 0; k < BK; k++) {
            float ar[TM], br[TN];
#pragma unroll
            for (int i = 0; i < TM; i++) ar[i] = As[k][ty * TM + i];
#pragma unroll
            for (int j = 0; j < TN; j++) br[j] = Bs[k][tx * TN + j];
#pragma unroll
            for (int i = 0; i < TM; i++)
#pragma unroll
                for (int j = 0; j < TN; j++)
                    acc[i][j] = fmaf(ar[i], br[j], acc[i][j]);
        }
        __syncthreads();
    }

    // Epilogue: add bias, store
#pragma unroll
    for (int i = 0; i < TM; i++) {
        const size_t row = (size_t)(bm + ty * TM + i);
#pragma unroll
        for (int j = 0; j < TN; j += 4) {
            int col = bn + tx * TN + j;
            float4 v;
            v.x = acc[i][j + 0] + bias[col + 0];
            v.y = acc[i][j + 1] + bias[col + 1];
            v.z = acc[i][j + 2] + bias[col + 2];
            v.w = acc[i][j + 3] + bias[col + 3];
            *reinterpret_cast<float4*>(&C[row * N + col]) = v;
        }
    }
}

// ---------------------------------------------------------------------------
// Chunked parallel scan over L:  h_t = a*h_{t-1} + b_t, a = sigmoid(A[h])
// Phase A: local inclusive scan inside each chunk of 128, record chunk-end.
// Phase B: serial scan over the 16 chunk carries per channel (exclusive out).
// Phase C: h_t += a^(i+1) * carry_in  for local index i within chunk.
// Layout of b: [B, L, H] -> h innermost => coalesced across threads.
// ---------------------------------------------------------------------------
__device__ __forceinline__ float dsigmoid(float x) {
    return 1.0f / (1.0f + expf(-x));
}

__global__ void scan_phaseA(float* __restrict__ bbuf, const float* __restrict__ Araw,
                            float* __restrict__ carry)
{
    int idx = blockIdx.x * blockDim.x + threadIdx.x;   // [B, NC, H]
    int h = idx & (H_ - 1);
    int c = (idx >> 12) & (NC_ - 1);
    int bb = idx >> 16;
    float a = dsigmoid(Araw[h]);
    size_t base = ((size_t)bb * L_ + (size_t)c * CHUNK_) * H_ + h;
    float s = 0.0f;
#pragma unroll 8
    for (int i = 0; i < CHUNK_; i++) {
        float v = bbuf[base + (size_t)i * H_];
        s = fmaf(a, s, v);
        bbuf[base + (size_t)i * H_] = s;
    }
    carry[idx] = s;
}

__global__ void scan_phaseB(const float* __restrict__ carry,
                            const float* __restrict__ Araw,
                            float* __restrict__ hprev)
{
    int idx = blockIdx.x * blockDim.x + threadIdx.x;   // [B, H]
    int h = idx & (H_ - 1);
    int bb = idx >> 12;
    float a = dsigmoid(Araw[h]);
    float aC = a;
#pragma unroll
    for (int i = 0; i < 7; i++) aC *= aC;              // a^128 via squaring
    float run = 0.0f;
#pragma unroll
    for (int c = 0; c < NC_; c++) {
        size_t off = ((size_t)bb * NC_ + c) * H_ + h;
        hprev[off] = run;                              // exclusive carry-in
        run = fmaf(aC, run, carry[off]);
    }
}

__global__ void scan_phaseC(float* __restrict__ bbuf, const float* __restrict__ Araw,
                            const float* __restrict__ hprev)
{
    int idx = blockIdx.x * blockDim.x + threadIdx.x;   // [B, NC, H]
    int h = idx & (H_ - 1);
    int c = (idx >> 12) & (NC_ - 1);
    int bb = idx >> 16;
    if (c == 0) return;                                // carry-in is zero
    float Hp = hprev[idx];
    float a = dsigmoid(Araw[h]);
    size_t base = ((size_t)bb * L_ + (size_t)c * CHUNK_) * H_ + h;
    float p = a;                                       // a^(i+1)
#pragma unroll 8
    for (int i = 0; i < CHUNK_; i++) {
        size_t off = base + (size_t)i * H_;
        bbuf[off] = fmaf(p, Hp, bbuf[off]);
        p *= a;
    }
}

// ---------------------------------------------------------------------------
extern "C" void kernel_launch(void* const* d_in, const int* in_sizes, int n_in,
                              void* d_out, int out_size)
{
    const float* x  = (const float*)d_in[0];   // [B, L, D]
    const float* WB = (const float*)d_in[1];   // [H, D]
    const float* bB = (const float*)d_in[2];   // [H]
    const float* WC = (const float*)d_in[3];   // [D, H]
    const float* bC = (const float*)d_in[4];   // [D]
    const float* A  = (const float*)d_in[5];   // [H]
    float* out = (float*)d_out;                // [B, L, D]

    float *bbuf, *carry, *hprev;
    cudaGetSymbolAddress((void**)&bbuf, g_b);
    cudaGetSymbolAddress((void**)&carry, g_carry);
    cudaGetSymbolAddress((void**)&hprev, g_hprev);

    dim3 blk(256);

    // GEMM1: b = x @ WB^T + bB   (M=8192, N=4096, K=256)
    sgemm_nt_bias<128, 128, 16, 8, 8>
        <<<dim3(H_ / 128, M_ / 128), blk>>>(x, WB, bB, bbuf, M_, H_, D_);

    // Scan over L (in place on bbuf)
    scan_phaseA<<<(B_ * NC_ * H_) / 256, blk>>>(bbuf, A, carry);
    scan_phaseB<<<(B_ * H_) / 256, blk>>>(carry, A, hprev);
    scan_phaseC<<<(B_ * NC_ * H_) / 256, blk>>>(bbuf, A, hprev);

    // GEMM2: out = h @ WC^T + bC  (M=8192, N=256, K=4096)
    sgemm_nt_bias<128, 128, 16, 8, 8>
        <<<dim3(D_ / 128, M_ / 128), blk>>>(bbuf, WC, bC, out, M_, D_, H_);
}

// round 3
// speedup vs baseline: 2.6236x; 2.6236x over previous
#include <cuda_runtime.h>
#include <cuda_bf16.h>
#include <cstdint>
#include <math.h>

// ---------------------------------------------------------------------------
// Problem constants
// ---------------------------------------------------------------------------
#define B_ 4
#define L_ 2048
#define D_ 256
#define H_ 4096
#define M_ (B_ * L_)          // 8192
#define CHUNK_ 128
#define NC_ (L_ / CHUNK_)     // 16

// ---------------------------------------------------------------------------
// Scratch (device globals; no allocation allowed)
// ---------------------------------------------------------------------------
__device__ __align__(256) float         g_b[(size_t)M_ * H_];      // 128 MB
__device__ __align__(256) __nv_bfloat16 g_hhi[(size_t)M_ * H_];
__device__ __align__(256) __nv_bfloat16 g_hlo[(size_t)M_ * H_];
__device__ __align__(256) __nv_bfloat16 g_xhi[(size_t)M_ * D_];
__device__ __align__(256) __nv_bfloat16 g_xlo[(size_t)M_ * D_];
__device__ __align__(256) __nv_bfloat16 g_wbhi[(size_t)H_ * D_];
__device__ __align__(256) __nv_bfloat16 g_wblo[(size_t)H_ * D_];
__device__ __align__(256) __nv_bfloat16 g_wchi[(size_t)D_ * H_];
__device__ __align__(256) __nv_bfloat16 g_wclo[(size_t)D_ * H_];
__device__ __align__(256) float         g_carry[B_ * NC_ * H_];
__device__ __align__(256) float         g_hprev[B_ * NC_ * H_];

// ---------------------------------------------------------------------------
// PTX helpers (baseline ISA only: cp.async / ldmatrix / mma.sync)
// ---------------------------------------------------------------------------
__device__ __forceinline__ uint32_t smem_to_u32(const void* p) {
    uint32_t a;
    asm("{ .reg .u64 t; cvta.to.shared.u64 t, %1; cvt.u32.u64 %0, t; }" : "=r"(a) : "l"(p));
    return a;
}
__device__ __forceinline__ void cp_async16(uint32_t dst, const void* src) {
    asm volatile("cp.async.cg.shared.global [%0], [%1], 16;" :: "r"(dst), "l"(src) : "memory");
}
__device__ __forceinline__ void cp_commit() {
    asm volatile("cp.async.commit_group;" ::: "memory");
}
__device__ __forceinline__ void cp_wait2() {
    asm volatile("cp.async.wait_group 2;" ::: "memory");
}
__device__ __forceinline__ void ldsm_x4(uint32_t* r, uint32_t addr) {
    asm volatile("ldmatrix.sync.aligned.m8n8.x4.shared.b16 {%0,%1,%2,%3}, [%4];"
                 : "=r"(r[0]), "=r"(r[1]), "=r"(r[2]), "=r"(r[3]) : "r"(addr));
}
__device__ __forceinline__ void mma_bf16(float* c, const uint32_t* a, const uint32_t* b) {
    asm volatile(
        "mma.sync.aligned.m16n8k16.row.col.f32.bf16.bf16.f32 "
        "{%0,%1,%2,%3}, {%4,%5,%6,%7}, {%8,%9}, {%0,%1,%2,%3};"
        : "+f"(c[0]), "+f"(c[1]), "+f"(c[2]), "+f"(c[3])
        : "r"(a[0]), "r"(a[1]), "r"(a[2]), "r"(a[3]), "r"(b[0]), "r"(b[1]));
}

// Swizzle: 64B rows, 4x 16B lanes; lane ^= (row%4) ^ ((row/4)%4)
__device__ __forceinline__ uint32_t sw_off(int row, int lane) {
    return (uint32_t)(row * 64 + ((lane ^ (row & 3) ^ ((row >> 2) & 3)) << 4));
}

// ---------------------------------------------------------------------------
// Split fp32 -> (hi, lo) bf16
// ---------------------------------------------------------------------------
__global__ void split_f32(const float* __restrict__ src,
                          __nv_bfloat16* __restrict__ hi,
                          __nv_bfloat16* __restrict__ lo, int n4)
{
    int i = blockIdx.x * blockDim.x + threadIdx.x;
    if (i >= n4) return;
    float4 v = reinterpret_cast<const float4*>(src)[i];
    __nv_bfloat16 h0 = __float2bfloat16_rn(v.x);
    __nv_bfloat16 h1 = __float2bfloat16_rn(v.y);
    __nv_bfloat16 h2 = __float2bfloat16_rn(v.z);
    __nv_bfloat16 h3 = __float2bfloat16_rn(v.w);
    __nv_bfloat16 l0 = __float2bfloat16_rn(v.x - __bfloat162float(h0));
    __nv_bfloat16 l1 = __float2bfloat16_rn(v.y - __bfloat162float(h1));
    __nv_bfloat16 l2 = __float2bfloat16_rn(v.z - __bfloat162float(h2));
    __nv_bfloat16 l3 = __float2bfloat16_rn(v.w - __bfloat162float(h3));
    reinterpret_cast<__nv_bfloat162*>(hi)[2 * i + 0] = __halves2bfloat162(h0, h1);
    reinterpret_cast<__nv_bfloat162*>(hi)[2 * i + 1] = __halves2bfloat162(h2, h3);
    reinterpret_cast<__nv_bfloat162*>(lo)[2 * i + 0] = __halves2bfloat162(l0, l1);
    reinterpret_cast<__nv_bfloat162*>(lo)[2 * i + 1] = __halves2bfloat162(l2, l3);
}

// ---------------------------------------------------------------------------
// Split-bf16 x3 GEMM (NT) via mma.sync:
//   C[M,N] = (Ahi+Alo)[M,K] @ ((Bhi+Blo)[N,K])^T + bias[N]
// BM=128, BN=128, BK=32; 8 warps (4m x 2n), warp tile 32x64.
// 4-stage cp.async pipeline; 32KB/stage (Ahi|Alo|Bhi|Blo 8KB each, 64B rows).
// ---------------------------------------------------------------------------
#define BM_ 128
#define BN_ 128
#define BK_ 32
#define NSTAGE_ 4
#define STG_ 32768
#define T_AHI 0
#define T_ALO 8192
#define T_BHI 16384
#define T_BLO 24576

__device__ __forceinline__ void load_stage(
    uint32_t st, int tid, const char* Ahi, const char* Alo,
    const char* Bhi, const char* Blo, size_t rowbytes, int bm, int bn, int k0byte)
{
#pragma unroll
    for (int i = 0; i < 2; i++) {
        int l = tid + i * 256;          // 0..511 lanes of 16B
        int r = l >> 2, c = l & 3;
        uint32_t sw = sw_off(r, c);
        size_t ga = (size_t)(bm + r) * rowbytes + k0byte + c * 16;
        size_t gb = (size_t)(bn + r) * rowbytes + k0byte + c * 16;
        cp_async16(st + T_AHI + sw, Ahi + ga);
        cp_async16(st + T_ALO + sw, Alo + ga);
        cp_async16(st + T_BHI + sw, Bhi + gb);
        cp_async16(st + T_BLO + sw, Blo + gb);
    }
}

__global__ __launch_bounds__(256)
void gemm_split3(const __nv_bfloat16* __restrict__ Ahi, const __nv_bfloat16* __restrict__ Alo,
                 const __nv_bfloat16* __restrict__ Bhi, const __nv_bfloat16* __restrict__ Blo,
                 const float* __restrict__ bias, float* __restrict__ C,
                 int N, int K)
{
    extern __shared__ char smem[];
    const uint32_t sb = smem_to_u32(smem);
    const int tid = threadIdx.x;
    const int wid = tid >> 5, lid = tid & 31;
    const int wm = wid & 3, wn = wid >> 2;        // 4 x 2 warp grid
    const int bm = blockIdx.y * BM_;
    const int bn = blockIdx.x * BN_;
    const size_t rowbytes = (size_t)K * 2;
    const int NKC = K / BK_;

    const char* pAh = (const char*)Ahi;
    const char* pAl = (const char*)Alo;
    const char* pBh = (const char*)Bhi;
    const char* pBl = (const char*)Blo;

    float acc[2][8][4];
#pragma unroll
    for (int mt = 0; mt < 2; mt++)
#pragma unroll
        for (int nt = 0; nt < 8; nt++)
#pragma unroll
            for (int j = 0; j < 4; j++) acc[mt][nt][j] = 0.0f;

    // Prologue: stages 0..2
#pragma unroll
    for (int s = 0; s < NSTAGE_ - 1; s++) {
        if (s < NKC) load_stage(sb + s * STG_, tid, pAh, pAl, pBh, pBl, rowbytes, bm, bn, s * BK_ * 2);
        cp_commit();
    }

#pragma unroll 1
    for (int kc = 0; kc < NKC; kc++) {
        cp_wait2();
        __syncthreads();
        // Issue stage kc+3
        {
            int nx = kc + NSTAGE_ - 1;
            if (nx < NKC)
                load_stage(sb + (nx & 3) * STG_, tid, pAh, pAl, pBh, pBl, rowbytes, bm, bn, nx * BK_ * 2);
            cp_commit();
        }
        const uint32_t st = sb + (kc & 3) * STG_;

#pragma unroll
        for (int kst = 0; kst < 2; kst++) {
            uint32_t ah[2][4], al[2][4], bh[4][4], bl[4][4];
#pragma unroll
            for (int mt = 0; mt < 2; mt++) {
                int row = wm * 32 + mt * 16 + (lid & 15);
                int lane = kst * 2 + (lid >> 4);
                uint32_t off = sw_off(row, lane);
                ldsm_x4(ah[mt], st + T_AHI + off);
                ldsm_x4(al[mt], st + T_ALO + off);
            }
#pragma unroll
            for (int nt2 = 0; nt2 < 4; nt2++) {
                int row = wn * 64 + nt2 * 16 + (lid & 7) + ((lid >> 4) << 3);
                int lane = kst * 2 + ((lid >> 3) & 1);
                uint32_t off = sw_off(row, lane);
                ldsm_x4(bh[nt2], st + T_BHI + off);
                ldsm_x4(bl[nt2], st + T_BLO + off);
            }
#pragma unroll
            for (int mt = 0; mt < 2; mt++)
#pragma unroll
                for (int nt = 0; nt < 8; nt++) {
                    const uint32_t* bfh = &bh[nt >> 1][(nt & 1) * 2];
                    const uint32_t* bfl = &bl[nt >> 1][(nt & 1) * 2];
                    mma_bf16(acc[mt][nt], ah[mt], bfh);   // hi*hi
                    mma_bf16(acc[mt][nt], al[mt], bfh);   // lo*hi
                    mma_bf16(acc[mt][nt], ah[mt], bfl);   // hi*lo
                }
        }
        __syncthreads();
    }

    // Epilogue: add bias, store fp32
    const int r0 = bm + wm * 32 + (lid >> 2);
    const int cq = (lid & 3) * 2;
#pragma unroll
    for (int mt = 0; mt < 2; mt++) {
#pragma unroll
        for (int nt = 0; nt < 8; nt++) {
            int col = bn + wn * 64 + nt * 8 + cq;
            float bx = bias[col], by = bias[col + 1];
            float2 v0 = make_float2(acc[mt][nt][0] + bx, acc[mt][nt][1] + by);
            float2 v1 = make_float2(acc[mt][nt][2] + bx, acc[mt][nt][3] + by);
            *reinterpret_cast<float2*>(&C[(size_t)(r0 + mt * 16) * N + col]) = v0;
            *reinterpret_cast<float2*>(&C[(size_t)(r0 + mt * 16 + 8) * N + col]) = v1;
        }
    }
}

// ---------------------------------------------------------------------------
// Scan:  h_t = a*h_{t-1} + b_t, a = sigmoid(A[h]); chunked over L
// ---------------------------------------------------------------------------
__device__ __forceinline__ float dsigmoid(float x) { return 1.0f / (1.0f + expf(-x)); }

__global__ void scan_reduceA(const float* __restrict__ bbuf, const float* __restrict__ Araw,
                             float* __restrict__ carry)
{
    int idx = blockIdx.x * blockDim.x + threadIdx.x;   // [B, NC, H]
    int h = idx & (H_ - 1);
    int c = (idx >> 12) & (NC_ - 1);
    int bb = idx >> 16;
    float a = dsigmoid(Araw[h]);
    size_t base = ((size_t)bb * L_ + (size_t)c * CHUNK_) * H_ + h;
    float s = 0.0f;
#pragma unroll 8
    for (int i = 0; i < CHUNK_; i++) s = fmaf(a, s, bbuf[base + (size_t)i * H_]);
    carry[idx] = s;
}

__global__ void scan_phaseB(const float* __restrict__ carry, const float* __restrict__ Araw,
                            float* __restrict__ hprev)
{
    int idx = blockIdx.x * blockDim.x + threadIdx.x;   // [B, H]
    int h = idx & (H_ - 1);
    int bb = idx >> 12;
    float a = dsigmoid(Araw[h]);
    float aC = a;
#pragma unroll
    for (int i = 0; i < 7; i++) aC *= aC;              // a^128
    float run = 0.0f;
#pragma unroll
    for (int c = 0; c < NC_; c++) {
        size_t off = ((size_t)bb * NC_ + c) * H_ + h;
        hprev[off] = run;
        run = fmaf(aC, run, carry[off]);
    }
}

__global__ void scan_phaseC(const float* __restrict__ bbuf, const float* __restrict__ Araw,
                            const float* __restrict__ hprev,
                            __nv_bfloat16* __restrict__ hhi, __nv_bfloat16* __restrict__ hlo)
{
    int idx = blockIdx.x * blockDim.x + threadIdx.x;   // [B, NC, H]
    int h = idx & (H_ - 1);
    int c = (idx >> 12) & (NC_ - 1);
    int bb = idx >> 16;
    float a = dsigmoid(Araw[h]);
    float Hp = hprev[idx];
    size_t base = ((size_t)bb * L_ + (size_t)c * CHUNK_) * H_ + h;
    float s = 0.0f, p = 1.0f;
#pragma unroll 8
    for (int i = 0; i < CHUNK_; i++) {
        size_t off = base + (size_t)i * H_;
        p *= a;                        // a^(i+1)
        s = fmaf(a, s, bbuf[off]);     // local inclusive scan
        float v = fmaf(p, Hp, s);      // + carry-in contribution
        __nv_bfloat16 hi = __float2bfloat16_rn(v);
        hhi[off] = hi;
        hlo[off] = __float2bfloat16_rn(v - __bfloat162float(hi));
    }
}

// ---------------------------------------------------------------------------
extern "C" void kernel_launch(void* const* d_in, const int* in_sizes, int n_in,
                              void* d_out, int out_size)
{
    const float* x  = (const float*)d_in[0];   // [B, L, D]
    const float* WB = (const float*)d_in[1];   // [H, D]
    const float* bB = (const float*)d_in[2];   // [H]
    const float* WC = (const float*)d_in[3];   // [D, H]
    const float* bC = (const float*)d_in[4];   // [D]
    const float* A  = (const float*)d_in[5];   // [H]
    float* out = (float*)d_out;                // [B, L, D]

    float *bbuf, *carry, *hprev;
    __nv_bfloat16 *xhi, *xlo, *wbhi, *wblo, *wchi, *wclo, *hhi, *hlo;
    cudaGetSymbolAddress((void**)&bbuf, g_b);
    cudaGetSymbolAddress((void**)&carry, g_carry);
    cudaGetSymbolAddress((void**)&hprev, g_hprev);
    cudaGetSymbolAddress((void**)&xhi, g_xhi);
    cudaGetSymbolAddress((void**)&xlo, g_xlo);
    cudaGetSymbolAddress((void**)&wbhi, g_wbhi);
    cudaGetSymbolAddress((void**)&wblo, g_wblo);
    cudaGetSymbolAddress((void**)&wchi, g_wchi);
    cudaGetSymbolAddress((void**)&wclo, g_wclo);
    cudaGetSymbolAddress((void**)&hhi, g_hhi);
    cudaGetSymbolAddress((void**)&hlo, g_hlo);

    const int SMEM_G = NSTAGE_ * STG_;     // 128 KB
    cudaFuncSetAttribute(gemm_split3, cudaFuncAttributeMaxDynamicSharedMemorySize, SMEM_G);

    // Split inputs to bf16 hi/lo
    split_f32<<<(M_ * D_ / 4 + 255) / 256, 256>>>(x, xhi, xlo, M_ * D_ / 4);
    split_f32<<<(H_ * D_ / 4 + 255) / 256, 256>>>(WB, wbhi, wblo, H_ * D_ / 4);
    split_f32<<<(D_ * H_ / 4 + 255) / 256, 256>>>(WC, wchi, wclo, D_ * H_ / 4);

    // GEMM1: b = x @ WB^T + bB   (M=8192, N=4096, K=256)
    gemm_split3<<<dim3(H_ / BN_, M_ / BM_), 256, SMEM_G>>>(
        xhi, xlo, wbhi, wblo, bB, bbuf, H_, D_);

    // Scan over L
    scan_reduceA<<<(B_ * NC_ * H_) / 256, 256>>>(bbuf, A, carry);
    scan_phaseB<<<(B_ * H_) / 256, 256>>>(carry, A, hprev);
    scan_phaseC<<<(B_ * NC_ * H_) / 256, 256>>>(bbuf, A, hprev, hhi, hlo);

    // GEMM2: out = h @ WC^T + bC  (M=8192, N=256, K=4096)
    gemm_split3<<<dim3(D_ / BN_, M_ / BM_), 256, SMEM_G>>>(
        hhi, hlo, wchi, wclo, bC, out, D_, H_);
}

// round 4
// speedup vs baseline: 2.8203x; 1.0750x over previous
#include <cuda_runtime.h>
#include <cuda_bf16.h>
#include <cstdint>
#include <math.h>

// ---------------------------------------------------------------------------
// Problem constants
// ---------------------------------------------------------------------------
#define B_ 4
#define L_ 2048
#define D_ 256
#define H_ 4096
#define M_ (B_ * L_)          // 8192
#define CHUNK_ 128
#define NC_ (L_ / CHUNK_)     // 16

// ---------------------------------------------------------------------------
// Scratch (device globals; no allocation allowed)
// g_b holds b [M,H] fp32 for the scan; after phaseC it is dead, so GEMM2's
// split-K partials (2 x M x D fp32 = 16MB) reuse its space.
// ---------------------------------------------------------------------------
__device__ __align__(256) float         g_b[(size_t)M_ * H_];      // 128 MB
__device__ __align__(256) __nv_bfloat16 g_hhi[(size_t)M_ * H_];
__device__ __align__(256) __nv_bfloat16 g_hlo[(size_t)M_ * H_];
__device__ __align__(256) __nv_bfloat16 g_xhi[(size_t)M_ * D_];
__device__ __align__(256) __nv_bfloat16 g_xlo[(size_t)M_ * D_];
__device__ __align__(256) __nv_bfloat16 g_wbhi[(size_t)H_ * D_];
__device__ __align__(256) __nv_bfloat16 g_wblo[(size_t)H_ * D_];
__device__ __align__(256) __nv_bfloat16 g_wchi[(size_t)D_ * H_];
__device__ __align__(256) __nv_bfloat16 g_wclo[(size_t)D_ * H_];
__device__ __align__(256) float         g_carry[B_ * NC_ * H_];
__device__ __align__(256) float         g_hprev[B_ * NC_ * H_];

// ---------------------------------------------------------------------------
// PTX helpers (baseline ISA only: cp.async / ldmatrix / mma.sync)
// ---------------------------------------------------------------------------
__device__ __forceinline__ uint32_t smem_to_u32(const void* p) {
    uint32_t a;
    asm("{ .reg .u64 t; cvta.to.shared.u64 t, %1; cvt.u32.u64 %0, t; }" : "=r"(a) : "l"(p));
    return a;
}
__device__ __forceinline__ void cp_async16(uint32_t dst, const void* src) {
    asm volatile("cp.async.cg.shared.global [%0], [%1], 16;" :: "r"(dst), "l"(src) : "memory");
}
__device__ __forceinline__ void cp_commit() {
    asm volatile("cp.async.commit_group;" ::: "memory");
}
__device__ __forceinline__ void cp_wait1() {
    asm volatile("cp.async.wait_group 1;" ::: "memory");
}
__device__ __forceinline__ void ldsm_x4(uint32_t* r, uint32_t addr) {
    asm volatile("ldmatrix.sync.aligned.m8n8.x4.shared.b16 {%0,%1,%2,%3}, [%4];"
                 : "=r"(r[0]), "=r"(r[1]), "=r"(r[2]), "=r"(r[3]) : "r"(addr));
}
__device__ __forceinline__ void mma_bf16(float* c, const uint32_t* a, const uint32_t* b) {
    asm volatile(
        "mma.sync.aligned.m16n8k16.row.col.f32.bf16.bf16.f32 "
        "{%0,%1,%2,%3}, {%4,%5,%6,%7}, {%8,%9}, {%0,%1,%2,%3};"
        : "+f"(c[0]), "+f"(c[1]), "+f"(c[2]), "+f"(c[3])
        : "r"(a[0]), "r"(a[1]), "r"(a[2]), "r"(a[3]), "r"(b[0]), "r"(b[1]));
}

// Swizzle: 64B rows, 4x 16B lanes; lane ^= (row%4) ^ ((row/4)%4)
__device__ __forceinline__ uint32_t sw_off(int row, int lane) {
    return (uint32_t)(row * 64 + ((lane ^ (row & 3) ^ ((row >> 2) & 3)) << 4));
}

// ---------------------------------------------------------------------------
// Split fp32 -> (hi, lo) bf16
// ---------------------------------------------------------------------------
__global__ void split_f32(const float* __restrict__ src,
                          __nv_bfloat16* __restrict__ hi,
                          __nv_bfloat16* __restrict__ lo, int n4)
{
    int i = blockIdx.x * blockDim.x + threadIdx.x;
    if (i >= n4) return;
    float4 v = reinterpret_cast<const float4*>(src)[i];
    __nv_bfloat16 h0 = __float2bfloat16_rn(v.x);
    __nv_bfloat16 h1 = __float2bfloat16_rn(v.y);
    __nv_bfloat16 h2 = __float2bfloat16_rn(v.z);
    __nv_bfloat16 h3 = __float2bfloat16_rn(v.w);
    __nv_bfloat16 l0 = __float2bfloat16_rn(v.x - __bfloat162float(h0));
    __nv_bfloat16 l1 = __float2bfloat16_rn(v.y - __bfloat162float(h1));
    __nv_bfloat16 l2 = __float2bfloat16_rn(v.z - __bfloat162float(h2));
    __nv_bfloat16 l3 = __float2bfloat16_rn(v.w - __bfloat162float(h3));
    reinterpret_cast<__nv_bfloat162*>(hi)[2 * i + 0] = __halves2bfloat162(h0, h1);
    reinterpret_cast<__nv_bfloat162*>(hi)[2 * i + 1] = __halves2bfloat162(h2, h3);
    reinterpret_cast<__nv_bfloat162*>(lo)[2 * i + 0] = __halves2bfloat162(l0, l1);
    reinterpret_cast<__nv_bfloat162*>(lo)[2 * i + 1] = __halves2bfloat162(l2, l3);
}

// ---------------------------------------------------------------------------
// Split-bf16 x3 GEMM (NT) via mma.sync:
//   C[M,N] (+)= (Ahi+Alo)[M,Klen] @ ((Bhi+Blo)[N,Klen])^T (+ bias[N])
// BM=128, BN=128, BK=32; 8 warps (4m x 2n), warp tile 32x64.
// 3-stage cp.async pipeline; 32KB/stage -> 96KB smem -> 2 CTAs/SM.
// gridDim.z = split-K factor; block z handles K slice [z*Klen, (z+1)*Klen),
// writing to C + z*zstride. bias may be null (split-K partials).
// ---------------------------------------------------------------------------
#define BM_ 128
#define BN_ 128
#define BK_ 32
#define NSTAGE_ 3
#define STG_ 32768
#define T_AHI 0
#define T_ALO 8192
#define T_BHI 16384
#define T_BLO 24576

__device__ __forceinline__ void load_stage(
    uint32_t st, int tid, const char* Ahi, const char* Alo,
    const char* Bhi, const char* Blo, size_t rowbytes, int bm, int bn, int k0byte)
{
#pragma unroll
    for (int i = 0; i < 2; i++) {
        int l = tid + i * 256;          // 0..511 lanes of 16B
        int r = l >> 2, c = l & 3;
        uint32_t sw = sw_off(r, c);
        size_t ga = (size_t)(bm + r) * rowbytes + k0byte + c * 16;
        size_t gb = (size_t)(bn + r) * rowbytes + k0byte + c * 16;
        cp_async16(st + T_AHI + sw, Ahi + ga);
        cp_async16(st + T_ALO + sw, Alo + ga);
        cp_async16(st + T_BHI + sw, Bhi + gb);
        cp_async16(st + T_BLO + sw, Blo + gb);
    }
}

__global__ __launch_bounds__(256, 2)
void gemm_split3(const __nv_bfloat16* __restrict__ Ahi, const __nv_bfloat16* __restrict__ Alo,
                 const __nv_bfloat16* __restrict__ Bhi, const __nv_bfloat16* __restrict__ Blo,
                 const float* __restrict__ bias, float* __restrict__ C,
                 int N, int K, int Klen, size_t zstride)
{
    extern __shared__ char smem[];
    const uint32_t sb = smem_to_u32(smem);
    const int tid = threadIdx.x;
    const int wid = tid >> 5, lid = tid & 31;
    const int wm = wid & 3, wn = wid >> 2;        // 4 x 2 warp grid
    const int bm = blockIdx.y * BM_;
    const int bn = blockIdx.x * BN_;
    const size_t rowbytes = (size_t)K * 2;
    const int NKC = Klen / BK_;
    const size_t kofs = (size_t)blockIdx.z * Klen * 2;   // byte offset into rows

    const char* pAh = (const char*)Ahi + kofs;
    const char* pAl = (const char*)Alo + kofs;
    const char* pBh = (const char*)Bhi + kofs;
    const char* pBl = (const char*)Blo + kofs;
    C += (size_t)blockIdx.z * zstride;

    float acc[2][8][4];
#pragma unroll
    for (int mt = 0; mt < 2; mt++)
#pragma unroll
        for (int nt = 0; nt < 8; nt++)
#pragma unroll
            for (int j = 0; j < 4; j++) acc[mt][nt][j] = 0.0f;

    // Prologue: stages 0..1
#pragma unroll
    for (int s = 0; s < NSTAGE_ - 1; s++) {
        if (s < NKC) load_stage(sb + s * STG_, tid, pAh, pAl, pBh, pBl, rowbytes, bm, bn, s * BK_ * 2);
        cp_commit();
    }

#pragma unroll 1
    for (int kc = 0; kc < NKC; kc++) {
        cp_wait1();
        __syncthreads();
        // Issue stage kc+2
        {
            int nx = kc + NSTAGE_ - 1;
            if (nx < NKC)
                load_stage(sb + (nx % NSTAGE_) * STG_, tid, pAh, pAl, pBh, pBl, rowbytes, bm, bn, nx * BK_ * 2);
            cp_commit();
        }
        const uint32_t st = sb + (kc % NSTAGE_) * STG_;

#pragma unroll
        for (int kst = 0; kst < 2; kst++) {
            uint32_t ah[2][4], al[2][4], bh[4][4], bl[4][4];
#pragma unroll
            for (int mt = 0; mt < 2; mt++) {
                int row = wm * 32 + mt * 16 + (lid & 15);
                int lane = kst * 2 + (lid >> 4);
                uint32_t off = sw_off(row, lane);
                ldsm_x4(ah[mt], st + T_AHI + off);
                ldsm_x4(al[mt], st + T_ALO + off);
            }
#pragma unroll
            for (int nt2 = 0; nt2 < 4; nt2++) {
                int row = wn * 64 + nt2 * 16 + (lid & 7) + ((lid >> 4) << 3);
                int lane = kst * 2 + ((lid >> 3) & 1);
                uint32_t off = sw_off(row, lane);
                ldsm_x4(bh[nt2], st + T_BHI + off);
                ldsm_x4(bl[nt2], st + T_BLO + off);
            }
#pragma unroll
            for (int mt = 0; mt < 2; mt++)
#pragma unroll
                for (int nt = 0; nt < 8; nt++) {
                    const uint32_t* bfh = &bh[nt >> 1][(nt & 1) * 2];
                    const uint32_t* bfl = &bl[nt >> 1][(nt & 1) * 2];
                    mma_bf16(acc[mt][nt], ah[mt], bfh);   // hi*hi
                    mma_bf16(acc[mt][nt], al[mt], bfh);   // lo*hi
                    mma_bf16(acc[mt][nt], ah[mt], bfl);   // hi*lo
                }
        }
        __syncthreads();
    }

    // Epilogue: add bias (if any), store fp32
    const int r0 = bm + wm * 32 + (lid >> 2);
    const int cq = (lid & 3) * 2;
#pragma unroll
    for (int mt = 0; mt < 2; mt++) {
#pragma unroll
        for (int nt = 0; nt < 8; nt++) {
            int col = bn + wn * 64 + nt * 8 + cq;
            float bx = 0.0f, by = 0.0f;
            if (bias) { bx = bias[col]; by = bias[col + 1]; }
            float2 v0 = make_float2(acc[mt][nt][0] + bx, acc[mt][nt][1] + by);
            float2 v1 = make_float2(acc[mt][nt][2] + bx, acc[mt][nt][3] + by);
            *reinterpret_cast<float2*>(&C[(size_t)(r0 + mt * 16) * N + col]) = v0;
            *reinterpret_cast<float2*>(&C[(size_t)(r0 + mt * 16 + 8) * N + col]) = v1;
        }
    }
}

// Split-K reduce: out[i] = p0[i] + p1[i] + bias[col]
__global__ void reduce_splitk(const float* __restrict__ part, const float* __restrict__ bias,
                              float* __restrict__ out, int n4, size_t zstride4, int Nmask4)
{
    int i = blockIdx.x * blockDim.x + threadIdx.x;
    if (i >= n4) return;
    float4 a = reinterpret_cast<const float4*>(part)[i];
    float4 b = reinterpret_cast<const float4*>(part)[i + zstride4];
    int col = (i & Nmask4) * 4;
    float4 v;
    v.x = a.x + b.x + bias[col + 0];
    v.y = a.y + b.y + bias[col + 1];
    v.z = a.z + b.z + bias[col + 2];
    v.w = a.w + b.w + bias[col + 3];
    reinterpret_cast<float4*>(out)[i] = v;
}

// ---------------------------------------------------------------------------
// Scan:  h_t = a*h_{t-1} + b_t, a = sigmoid(A[h]); chunked over L
// ---------------------------------------------------------------------------
__device__ __forceinline__ float dsigmoid(float x) { return 1.0f / (1.0f + expf(-x)); }

__global__ void scan_reduceA(const float* __restrict__ bbuf, const float* __restrict__ Araw,
                             float* __restrict__ carry)
{
    int idx = blockIdx.x * blockDim.x + threadIdx.x;   // [B, NC, H]
    int h = idx & (H_ - 1);
    int c = (idx >> 12) & (NC_ - 1);
    int bb = idx >> 16;
    float a = dsigmoid(Araw[h]);
    size_t base = ((size_t)bb * L_ + (size_t)c * CHUNK_) * H_ + h;
    float s = 0.0f;
#pragma unroll 8
    for (int i = 0; i < CHUNK_; i++) s = fmaf(a, s, bbuf[base + (size_t)i * H_]);
    carry[idx] = s;
}

__global__ void scan_phaseB(const float* __restrict__ carry, const float* __restrict__ Araw,
                            float* __restrict__ hprev)
{
    int idx = blockIdx.x * blockDim.x + threadIdx.x;   // [B, H]
    int h = idx & (H_ - 1);
    int bb = idx >> 12;
    float a = dsigmoid(Araw[h]);
    float aC = a;
#pragma unroll
    for (int i = 0; i < 7; i++) aC *= aC;              // a^128
    float run = 0.0f;
#pragma unroll
    for (int c = 0; c < NC_; c++) {
        size_t off = ((size_t)bb * NC_ + c) * H_ + h;
        hprev[off] = run;
        run = fmaf(aC, run, carry[off]);
    }
}

__global__ void scan_phaseC(const float* __restrict__ bbuf, const float* __restrict__ Araw,
                            const float* __restrict__ hprev,
                            __nv_bfloat16* __restrict__ hhi, __nv_bfloat16* __restrict__ hlo)
{
    int idx = blockIdx.x * blockDim.x + threadIdx.x;   // [B, NC, H]
    int h = idx & (H_ - 1);
    int c = (idx >> 12) & (NC_ - 1);
    int bb = idx >> 16;
    float a = dsigmoid(Araw[h]);
    float Hp = hprev[idx];
    size_t base = ((size_t)bb * L_ + (size_t)c * CHUNK_) * H_ + h;
    float s = 0.0f, p = 1.0f;
#pragma unroll 8
    for (int i = 0; i < CHUNK_; i++) {
        size_t off = base + (size_t)i * H_;
        p *= a;                        // a^(i+1)
        s = fmaf(a, s, bbuf[off]);     // local inclusive scan
        float v = fmaf(p, Hp, s);      // + carry-in contribution
        __nv_bfloat16 hi = __float2bfloat16_rn(v);
        hhi[off] = hi;
        hlo[off] = __float2bfloat16_rn(v - __bfloat162float(hi));
    }
}

// ---------------------------------------------------------------------------
extern "C" void kernel_launch(void* const* d_in, const int* in_sizes, int n_in,
                              void* d_out, int out_size)
{
    const float* x  = (const float*)d_in[0];   // [B, L, D]
    const float* WB = (const float*)d_in[1];   // [H, D]
    const float* bB = (const float*)d_in[2];   // [H]
    const float* WC = (const float*)d_in[3];   // [D, H]
    const float* bC = (const float*)d_in[4];   // [D]
    const float* A  = (const float*)d_in[5];   // [H]
    float* out = (float*)d_out;                // [B, L, D]

    float *bbuf, *carry, *hprev;
    __nv_bfloat16 *xhi, *xlo, *wbhi, *wblo, *wchi, *wclo, *hhi, *hlo;
    cudaGetSymbolAddress((void**)&bbuf, g_b);
    cudaGetSymbolAddress((void**)&carry, g_carry);
    cudaGetSymbolAddress((void**)&hprev, g_hprev);
    cudaGetSymbolAddress((void**)&xhi, g_xhi);
    cudaGetSymbolAddress((void**)&xlo, g_xlo);
    cudaGetSymbolAddress((void**)&wbhi, g_wbhi);
    cudaGetSymbolAddress((void**)&wblo, g_wblo);
    cudaGetSymbolAddress((void**)&wchi, g_wchi);
    cudaGetSymbolAddress((void**)&wclo, g_wclo);
    cudaGetSymbolAddress((void**)&hhi, g_hhi);
    cudaGetSymbolAddress((void**)&hlo, g_hlo);

    const int SMEM_G = NSTAGE_ * STG_;     // 96 KB -> 2 CTAs/SM
    cudaFuncSetAttribute(gemm_split3, cudaFuncAttributeMaxDynamicSharedMemorySize, SMEM_G);

    // Split inputs to bf16 hi/lo
    split_f32<<<(M_ * D_ / 4 + 255) / 256, 256>>>(x, xhi, xlo, M_ * D_ / 4);
    split_f32<<<(H_ * D_ / 4 + 255) / 256, 256>>>(WB, wbhi, wblo, H_ * D_ / 4);
    split_f32<<<(D_ * H_ / 4 + 255) / 256, 256>>>(WC, wchi, wclo, D_ * H_ / 4);

    // GEMM1: b = x @ WB^T + bB   (M=8192, N=4096, K=256)
    gemm_split3<<<dim3(H_ / BN_, M_ / BM_, 1), 256, SMEM_G>>>(
        xhi, xlo, wbhi, wblo, bB, bbuf, H_, D_, D_, 0);

    // Scan over L
    scan_reduceA<<<(B_ * NC_ * H_) / 256, 256>>>(bbuf, A, carry);
    scan_phaseB<<<(B_ * H_) / 256, 256>>>(carry, A, hprev);
    scan_phaseC<<<(B_ * NC_ * H_) / 256, 256>>>(bbuf, A, hprev, hhi, hlo);

    // GEMM2: out = h @ WC^T + bC  (M=8192, N=256, K=4096), split-K=2.
    // Partials go into g_b (dead after phaseC): 2 x 8M floats.
    const size_t zstride = (size_t)M_ * D_;
    gemm_split3<<<dim3(D_ / BN_, M_ / BM_, 2), 256, SMEM_G>>>(
        hhi, hlo, wchi, wclo, nullptr, bbuf, D_, H_, H_ / 2, zstride);
    reduce_splitk<<<(M_ * D_ / 4 + 255) / 256, 256>>>(
        bbuf, bC, out, M_ * D_ / 4, zstride / 4, (D_ / 4) - 1);
}